// round 12
// baseline (speedup 1.0000x reference)
#include <cuda_runtime.h>
#include <cstdint>
#include <cstddef>

#define BB 32
#define TT 64
#define DD 512
#define HH 512
#define VV 32000
#define LL 2
#define G4 2048           // 4*H
#define EOS_TOK 3
#define PAD_TOK 0

typedef unsigned long long ull;

// ---------------- persistent device state (no allocations allowed) ----------
__device__ float g_h[2][LL][BB][HH];   // parity ping-pong
__device__ float g_c[2][LL][BB][HH];
__device__ float g_x[2][BB][DD];
__device__ int   g_fin[BB];
__device__ unsigned long long g_arg[BB];
__device__ unsigned int g_tick;        // sampler ticket (reset by sampler)

// ---------------- 32-byte L2::evict_last load (sm_100a requires v8.b32) ------
__device__ __forceinline__ void ldg_el8(const float* __restrict__ p, float* v) {
    uint32_t r0, r1, r2, r3, r4, r5, r6, r7;
    asm volatile(
        "ld.global.nc.L2::evict_last.v8.b32 {%0,%1,%2,%3,%4,%5,%6,%7}, [%8];"
        : "=r"(r0), "=r"(r1), "=r"(r2), "=r"(r3),
          "=r"(r4), "=r"(r5), "=r"(r6), "=r"(r7)
        : "l"(p));
    v[0] = __uint_as_float(r0); v[1] = __uint_as_float(r1);
    v[2] = __uint_as_float(r2); v[3] = __uint_as_float(r3);
    v[4] = __uint_as_float(r4); v[5] = __uint_as_float(r5);
    v[6] = __uint_as_float(r6); v[7] = __uint_as_float(r7);
}

// ---------------- packed f32x2 helpers (sm_100a full-rate fp32) -------------
__device__ __forceinline__ ull pk2(float lo, float hi) {
    ull r; asm("mov.b64 %0, {%1, %2};" : "=l"(r) : "f"(lo), "f"(hi)); return r;
}
__device__ __forceinline__ void fma2(ull& d, ull a, ull b) {
    asm("fma.rn.f32x2 %0, %1, %2, %3;" : "=l"(d) : "l"(a), "l"(b), "l"(d));
}
__device__ __forceinline__ float2 upk2(ull v) {
    float2 f; asm("mov.b64 {%0, %1}, %2;" : "=f"(f.x), "=f"(f.y) : "l"(v)); return f;
}

// ---------------- XLA-exact f32 tanh (Eigen-style rational, fma chain) ------
__device__ __forceinline__ float tanh_xla(float x) {
    const float kClamp = 7.90531110763549805f;
    float xc = fminf(fmaxf(x, -kClamp), kClamp);
    float x2 = __fmul_rn(xc, xc);
    float p = __fmaf_rn(x2, -2.76076847742355e-16f, 2.00018790482477e-13f);
    p = __fmaf_rn(x2, p, -8.60467152213735e-11f);
    p = __fmaf_rn(x2, p,  5.12229709037114e-08f);
    p = __fmaf_rn(x2, p,  1.48572235717979e-05f);
    p = __fmaf_rn(x2, p,  6.37261928875436e-04f);
    p = __fmaf_rn(x2, p,  4.89352455891786e-03f);
    p = __fmul_rn(xc, p);
    float q = __fmaf_rn(x2, 1.19825839466702e-06f, 1.18534705686654e-04f);
    q = __fmaf_rn(x2, q, 2.26843463243900e-03f);
    q = __fmaf_rn(x2, q, 4.89352518554385e-03f);
    float r = __fdiv_rn(p, q);
    return (fabsf(x) < 0.0004f) ? x : r;
}

__device__ __forceinline__ float sigmoid_xla(float x) {
    float t = tanh_xla(__fmul_rn(0.5f, x));
    return __fadd_rn(0.5f, __fmul_rn(0.5f, t));
}

// ---------------- threefry2x32 (JAX-exact) ----------------------------------
__host__ __device__ __forceinline__ uint32_t rotl32(uint32_t v, int r) {
    return (v << r) | (v >> (32 - r));
}

__host__ __device__ __forceinline__ void threefry2x32(
    uint32_t k0, uint32_t k1, uint32_t x0, uint32_t x1,
    uint32_t& o0, uint32_t& o1)
{
    uint32_t ks2 = k0 ^ k1 ^ 0x1BD11BDAu;
    x0 += k0; x1 += k1;
#define TF_G(r0,r1,r2,r3,a0,a1)                         \
    x0 += x1; x1 = rotl32(x1, r0); x1 ^= x0;            \
    x0 += x1; x1 = rotl32(x1, r1); x1 ^= x0;            \
    x0 += x1; x1 = rotl32(x1, r2); x1 ^= x0;            \
    x0 += x1; x1 = rotl32(x1, r3); x1 ^= x0;            \
    x0 += (a0); x1 += (a1);
    TF_G(13, 15, 26,  6, k1,  ks2 + 1u)
    TF_G(17, 29, 16, 24, ks2, k0  + 2u)
    TF_G(13, 15, 26,  6, k0,  k1  + 3u)
    TF_G(17, 29, 16, 24, k1,  ks2 + 4u)
    TF_G(13, 15, 26,  6, ks2, k0  + 5u)
#undef TF_G
    o0 = x0; o1 = x1;
}

// ---------------- init ---------------------------------------------------------
__global__ void k_init(const float* __restrict__ iseq,
                       const float* __restrict__ he,
                       const float* __restrict__ ce,
                       float* __restrict__ h0, float* __restrict__ c0,
                       float* __restrict__ x0)
{
    int idx = blockIdx.x * blockDim.x + threadIdx.x;
    if (idx < LL * BB * HH) { h0[idx] = he[idx]; c0[idx] = ce[idx]; }
    if (idx < BB * DD) {
        int b = idx / DD, k = idx % DD;
        x0[idx] = iseq[(size_t)b * TT * DD + k];
    }
    if (idx < BB) g_fin[idx] = 0;
}

// ---------------- LSTM layer (R10 proven: v8 evict_last weights) -------------
__global__ void k_lstm(const float* __restrict__ xin,
                       const float* __restrict__ hin,
                       const float* __restrict__ cin,
                       float* __restrict__ hout,
                       float* __restrict__ cout,
                       const float* __restrict__ Wih,
                       const float* __restrict__ Whh,
                       const float* __restrict__ bih,
                       const float* __restrict__ bhh,
                       int clearArg)
{
    __shared__ float xs[64][34];
    __shared__ float hs[64][34];
    __shared__ float wis[64][17];
    __shared__ float whs[64][17];
    __shared__ float sg[16][34];

    int tid = threadIdx.x;
    int jbase = blockIdx.x * 4;
    if (clearArg && blockIdx.x == 0 && tid < BB) g_arg[tid] = 0ull;

    int tn = tid & 15;
    int tb = tid >> 4;
    int gate = tn >> 2, jj = tn & 3;
    int row = gate * HH + jbase + jj;

    int wmat = tid >> 7;            // 0 = Wih, 1 = Whh
    int wchk = tid & 127;
    int wr_  = wchk >> 3;           // row 0..15
    int wc_  = wchk & 7;            // chunk 0..7 (8 floats each)
    int wrg = wr_ >> 2, wrj = wr_ & 3;
    int wrow = wrg * HH + jbase + wrj;

    float a1x = 0.f, a1y = 0.f, a2x = 0.f, a2y = 0.f;

    for (int kt = 0; kt < DD; kt += 64) {
        __syncthreads();
#pragma unroll
        for (int i = 0; i < 8; ++i) {
            int idx = tid + 256 * i;
            int k = idx & 63, b = idx >> 6;
            xs[k][b] = xin[b * DD + kt + k];
            hs[k][b] = hin[b * HH + kt + k];
        }
        {
            float v[8];
            const float* src = (wmat == 0)
                ? &Wih[(size_t)wrow * DD + kt + 8 * wc_]
                : &Whh[(size_t)wrow * HH + kt + 8 * wc_];
            ldg_el8(src, v);
            float (*dst)[17] = (wmat == 0) ? wis : whs;
#pragma unroll
            for (int j = 0; j < 8; ++j) dst[8 * wc_ + j][wr_] = v[j];
        }
        __syncthreads();
#pragma unroll 16
        for (int k = 0; k < 64; ++k) {
            float2 xv = *(const float2*)&xs[k][2 * tb];
            float2 hv = *(const float2*)&hs[k][2 * tb];
            float wiv = wis[k][tn];
            float whv = whs[k][tn];
            a1x = __fmaf_rn(xv.x, wiv, a1x);
            a1y = __fmaf_rn(xv.y, wiv, a1y);
            a2x = __fmaf_rn(hv.x, whv, a2x);
            a2y = __fmaf_rn(hv.y, whv, a2y);
        }
    }

    float bi_ = bih[row], bh_ = bhh[row];
    float s0 = __fadd_rn(__fadd_rn(__fadd_rn(a1x, bi_), a2x), bh_);
    float s1 = __fadd_rn(__fadd_rn(__fadd_rn(a1y, bi_), a2y), bh_);
    __syncthreads();
    sg[tn][2 * tb]     = s0;
    sg[tn][2 * tb + 1] = s1;
    __syncthreads();

    if (tid < 128) {
        int b = tid & 31, j2 = tid >> 5;
        float iv = sg[0  + j2][b];
        float fv = sg[4  + j2][b];
        float gv = sg[8  + j2][b];
        float ov = sg[12 + j2][b];
        int j = jbase + j2;
        float si = sigmoid_xla(iv);
        float sf = sigmoid_xla(fv);
        float so = sigmoid_xla(ov);
        float tg = tanh_xla(gv);
        float c2 = __fadd_rn(__fmul_rn(sf, cin[b * HH + j]), __fmul_rn(si, tg));
        float h2 = __fmul_rn(so, tanh_xla(c2));
        cout[b * HH + j] = c2;
        hout[b * HH + j] = h2;
    }
}

// ---------------- logits GEMM: 128v x 16b blocks, grid (250,2) ----------------
// tn=tid&31 (4 v), tb=tid>>5 (2 b). fc_w: 2x v8 evict_last loads/thread/ktile
// (same per-thread MLP as R10, 2x the blocks in flight). h stored pre-packed
// (h,h) in smem -> inner loop has no movs. Chains bit-identical to R10.
__global__ void __launch_bounds__(256, 4)
k_logits(const float* __restrict__ hin,
         const float* __restrict__ fcw,
         const float* __restrict__ fcb,
         float* __restrict__ out,
         float* __restrict__ xout,
         const float* __restrict__ embed,
         float* __restrict__ tok_out,
         int t, int has_tok, uint32_t ka, uint32_t kb)
{
    __shared__ float ws[32][132];
    __shared__ ull   hs2[32][17];
    __shared__ int   stok[BB];
    __shared__ unsigned int s_last;

    int tid = threadIdx.x;
    int tn = tid & 31, tb = tid >> 5;
    int vbase = blockIdx.x * 128;
    int boff  = blockIdx.y * 16;

    ull acc01[2], acc23[2];
    acc01[0] = acc01[1] = acc23[0] = acc23[1] = 0ull;

    // prefetch: fc_w 2 x v8 per thread, h 2 floats per thread per ktile
    float wv8[2][8];
    float h0r, h1r;
    const int hk0 = tid & 31, hb0 = tid >> 5;          // b 0..7
    const int hb1 = (tid >> 5) + 8;                    // b 8..15
#pragma unroll
    for (int i = 0; i < 2; ++i) {
        int flat = tid + 256 * i;
        int n = flat >> 2, c = flat & 3;
        ldg_el8(&fcw[(size_t)(vbase + n) * HH + 8 * c], wv8[i]);
    }
    h0r = hin[(boff + hb0) * HH + hk0];
    h1r = hin[(boff + hb1) * HH + hk0];

    for (int kt = 0; kt < HH; kt += 32) {
        __syncthreads();
#pragma unroll
        for (int i = 0; i < 2; ++i) {
            int flat = tid + 256 * i;
            int n = flat >> 2, c = flat & 3;
#pragma unroll
            for (int j = 0; j < 8; ++j) ws[8 * c + j][n] = wv8[i][j];
        }
        hs2[hk0][hb0] = pk2(h0r, h0r);
        hs2[hk0][hb1] = pk2(h1r, h1r);
        __syncthreads();

        if (kt + 32 < HH) {
            int kt2 = kt + 32;
#pragma unroll
            for (int i = 0; i < 2; ++i) {
                int flat = tid + 256 * i;
                int n = flat >> 2, c = flat & 3;
                ldg_el8(&fcw[(size_t)(vbase + n) * HH + kt2 + 8 * c], wv8[i]);
            }
            h0r = hin[(boff + hb0) * HH + kt2 + hk0];
            h1r = hin[(boff + hb1) * HH + kt2 + hk0];
        }

#pragma unroll
        for (int k = 0; k < 32; ++k) {
            ull wv01 = *(const ull*)&ws[k][4 * tn];
            ull wv23 = *(const ull*)&ws[k][4 * tn + 2];
            ull h0 = hs2[k][2 * tb];
            ull h1 = hs2[k][2 * tb + 1];
            fma2(acc01[0], h0, wv01); fma2(acc23[0], h0, wv23);
            fma2(acc01[1], h1, wv01); fma2(acc23[1], h1, wv23);
        }
    }

    float4 bv = *(const float4*)&fcb[vbase + 4 * tn];

#pragma unroll
    for (int bi = 0; bi < 2; ++bi) {
        int b = boff + 2 * tb + bi;
        float2 a01 = upk2(acc01[bi]);
        float2 a23 = upk2(acc23[bi]);
        float4 lg;
        lg.x = __fadd_rn(a01.x, bv.x);
        lg.y = __fadd_rn(a01.y, bv.y);
        lg.z = __fadd_rn(a23.x, bv.z);
        lg.w = __fadd_rn(a23.y, bv.w);
        __stcs((float4*)&out[((size_t)b * TT + t) * VV + vbase + 4 * tn], lg);

        unsigned long long best = 0ull;
        float lgs[4] = {lg.x, lg.y, lg.z, lg.w};
#pragma unroll
        for (int ni = 0; ni < 4; ++ni) {
            int v = vbase + 4 * tn + ni;
            uint32_t i = (uint32_t)(b * VV + v);
            uint32_t o0, o1;
            threefry2x32(ka, kb, 0u, i, o0, o1);
            uint32_t bits = o0 ^ o1;
            float f = __uint_as_float((bits >> 9) | 0x3f800000u) - 1.0f;
            float u = fmaxf(1.17549435e-38f, f);
            float g = -logf(-logf(u));
            float val = __fadd_rn(lgs[ni], g);
            uint32_t ub = __float_as_uint(val);
            ub = (ub & 0x80000000u) ? ~ub : (ub | 0x80000000u);
            unsigned long long key = ((unsigned long long)ub << 32) |
                (unsigned long long)(0x7fffffffu - (uint32_t)v);
            if (key > best) best = key;
        }
#pragma unroll
        for (int o = 16; o; o >>= 1) {
            unsigned long long other = __shfl_down_sync(0xffffffffu, best, o);
            if (other > best) best = other;
        }
        if (tn == 0) atomicMax(&g_arg[b], best);
    }

    // ---- fused sampler: last of ALL blocks does token select + embed gather
    __threadfence();
    if (tid == 0) {
        unsigned int total = gridDim.x * gridDim.y;
        unsigned int v = atomicAdd(&g_tick, 1u);
        s_last = (v == total - 1u) ? 1u : 0u;
    }
    __syncthreads();
    if (s_last) {
        if (tid == 0) g_tick = 0u;
        __threadfence();
        if (tid < BB) {
            unsigned long long key = g_arg[tid];
            int sampled = 0x7fffffff - (int)(uint32_t)(key & 0xffffffffu);
            int fin = g_fin[tid];
            int token = fin ? PAD_TOK : sampled;
            g_fin[tid] = fin | (sampled == EOS_TOK);
            stok[tid] = token;
            if (has_tok) tok_out[(size_t)tid * TT + t] = (float)token;
        }
        __syncthreads();
        for (int i = tid; i < BB * DD / 4; i += 256) {
            int b = i >> 7;
            int c = i & 127;
            ((float4*)xout)[b * 128 + c] =
                ((const float4*)embed)[(size_t)stok[b] * 128 + c];
        }
    }
}

// ---------------- host launch --------------------------------------------------
extern "C" void kernel_launch(void* const* d_in, const int* in_sizes, int n_in,
                              void* d_out, int out_size)
{
    const float* input_seq = (const float*)d_in[0];
    const float* h_enc     = (const float*)d_in[1];
    const float* c_enc     = (const float*)d_in[2];
    const float* W_ih      = (const float*)d_in[3];
    const float* W_hh      = (const float*)d_in[4];
    const float* b_ih      = (const float*)d_in[5];
    const float* b_hh      = (const float*)d_in[6];
    const float* fc_w      = (const float*)d_in[7];
    const float* fc_b      = (const float*)d_in[8];
    const float* embed     = (const float*)d_in[9];
    float* out = (float*)d_out;

    long long need_tok = (long long)BB * TT * VV + (long long)BB * TT;
    int has_tok = ((long long)out_size >= need_tok) ? 1 : 0;
    float* tok_out = out + (size_t)BB * TT * VV;

    float *hb, *cb, *xb;
    cudaGetSymbolAddress((void**)&hb, g_h);
    cudaGetSymbolAddress((void**)&cb, g_c);
    cudaGetSymbolAddress((void**)&xb, g_x);
#define HP(p, lyr) (hb + (((p) * LL) + (lyr)) * (BB * HH))
#define CP(p, lyr) (cb + (((p) * LL) + (lyr)) * (BB * HH))
#define XP(p)      (xb + (p) * (BB * DD))

    k_init<<<64, 512>>>(input_seq, h_enc, c_enc, HP(0, 0), CP(0, 0), XP(0));

    for (int t = 0; t < TT; ++t) {
        int p = t & 1, q = p ^ 1;

        k_lstm<<<128, 256>>>(XP(p), HP(p, 0), CP(p, 0),
                             HP(q, 0), CP(q, 0),
                             W_ih, W_hh, b_ih, b_hh, /*clearArg=*/1);
        k_lstm<<<128, 256>>>(HP(q, 0), HP(p, 1), CP(p, 1),
                             HP(q, 1), CP(q, 1),
                             W_ih + (size_t)G4 * DD,
                             W_hh + (size_t)G4 * HH,
                             b_ih + G4, b_hh + G4, /*clearArg=*/0);

        uint32_t ka, kb;
        threefry2x32(0u, 42u, 0u, (uint32_t)t, ka, kb);

        k_logits<<<dim3(250, 2), 256>>>(HP(q, 1), fc_w, fc_b, out,
                                        XP(q), embed, tok_out, t, has_tok, ka, kb);
    }
#undef HP
#undef CP
#undef XP
}

// round 13
// speedup vs baseline: 1.4717x; 1.4717x over previous
#include <cuda_runtime.h>
#include <cstdint>
#include <cstddef>

#define BB 32
#define TT 64
#define DD 512
#define HH 512
#define VV 32000
#define LL 2
#define G4 2048           // 4*H
#define EOS_TOK 3
#define PAD_TOK 0

typedef unsigned long long ull;

// ---------------- persistent device state (no allocations allowed) ----------
__device__ float g_h[2][LL][BB][HH];   // parity ping-pong
__device__ float g_c[2][LL][BB][HH];
__device__ float g_x[2][BB][DD];
__device__ int   g_fin[BB];
__device__ unsigned long long g_arg[BB];
__device__ unsigned int g_tick;        // sampler ticket (reset by sampler)

// ---------------- 32-byte L2::evict_last load (sm_100a requires v8.b32) ------
__device__ __forceinline__ void ldg_el8(const float* __restrict__ p, float* v) {
    uint32_t r0, r1, r2, r3, r4, r5, r6, r7;
    asm volatile(
        "ld.global.nc.L2::evict_last.v8.b32 {%0,%1,%2,%3,%4,%5,%6,%7}, [%8];"
        : "=r"(r0), "=r"(r1), "=r"(r2), "=r"(r3),
          "=r"(r4), "=r"(r5), "=r"(r6), "=r"(r7)
        : "l"(p));
    v[0] = __uint_as_float(r0); v[1] = __uint_as_float(r1);
    v[2] = __uint_as_float(r2); v[3] = __uint_as_float(r3);
    v[4] = __uint_as_float(r4); v[5] = __uint_as_float(r5);
    v[6] = __uint_as_float(r6); v[7] = __uint_as_float(r7);
}

// ---------------- packed f32x2 helpers (sm_100a full-rate fp32) -------------
__device__ __forceinline__ ull pk2(float lo, float hi) {
    ull r; asm("mov.b64 %0, {%1, %2};" : "=l"(r) : "f"(lo), "f"(hi)); return r;
}
__device__ __forceinline__ void fma2(ull& d, ull a, ull b) {
    asm("fma.rn.f32x2 %0, %1, %2, %3;" : "=l"(d) : "l"(a), "l"(b), "l"(d));
}
__device__ __forceinline__ float2 upk2(ull v) {
    float2 f; asm("mov.b64 {%0, %1}, %2;" : "=f"(f.x), "=f"(f.y) : "l"(v)); return f;
}

// ---------------- XLA-exact f32 tanh (Eigen-style rational, fma chain) ------
__device__ __forceinline__ float tanh_xla(float x) {
    const float kClamp = 7.90531110763549805f;
    float xc = fminf(fmaxf(x, -kClamp), kClamp);
    float x2 = __fmul_rn(xc, xc);
    float p = __fmaf_rn(x2, -2.76076847742355e-16f, 2.00018790482477e-13f);
    p = __fmaf_rn(x2, p, -8.60467152213735e-11f);
    p = __fmaf_rn(x2, p,  5.12229709037114e-08f);
    p = __fmaf_rn(x2, p,  1.48572235717979e-05f);
    p = __fmaf_rn(x2, p,  6.37261928875436e-04f);
    p = __fmaf_rn(x2, p,  4.89352455891786e-03f);
    p = __fmul_rn(xc, p);
    float q = __fmaf_rn(x2, 1.19825839466702e-06f, 1.18534705686654e-04f);
    q = __fmaf_rn(x2, q, 2.26843463243900e-03f);
    q = __fmaf_rn(x2, q, 4.89352518554385e-03f);
    float r = __fdiv_rn(p, q);
    return (fabsf(x) < 0.0004f) ? x : r;
}

__device__ __forceinline__ float sigmoid_xla(float x) {
    float t = tanh_xla(__fmul_rn(0.5f, x));
    return __fadd_rn(0.5f, __fmul_rn(0.5f, t));
}

// ---------------- threefry2x32 (JAX-exact) ----------------------------------
__host__ __device__ __forceinline__ uint32_t rotl32(uint32_t v, int r) {
    return (v << r) | (v >> (32 - r));
}

__host__ __device__ __forceinline__ void threefry2x32(
    uint32_t k0, uint32_t k1, uint32_t x0, uint32_t x1,
    uint32_t& o0, uint32_t& o1)
{
    uint32_t ks2 = k0 ^ k1 ^ 0x1BD11BDAu;
    x0 += k0; x1 += k1;
#define TF_G(r0,r1,r2,r3,a0,a1)                         \
    x0 += x1; x1 = rotl32(x1, r0); x1 ^= x0;            \
    x0 += x1; x1 = rotl32(x1, r1); x1 ^= x0;            \
    x0 += x1; x1 = rotl32(x1, r2); x1 ^= x0;            \
    x0 += x1; x1 = rotl32(x1, r3); x1 ^= x0;            \
    x0 += (a0); x1 += (a1);
    TF_G(13, 15, 26,  6, k1,  ks2 + 1u)
    TF_G(17, 29, 16, 24, ks2, k0  + 2u)
    TF_G(13, 15, 26,  6, k0,  k1  + 3u)
    TF_G(17, 29, 16, 24, k1,  ks2 + 4u)
    TF_G(13, 15, 26,  6, ks2, k0  + 5u)
#undef TF_G
    o0 = x0; o1 = x1;
}

// ---------------- init ---------------------------------------------------------
__global__ void k_init(const float* __restrict__ iseq,
                       const float* __restrict__ he,
                       const float* __restrict__ ce,
                       float* __restrict__ h0, float* __restrict__ c0,
                       float* __restrict__ x0)
{
    int idx = blockIdx.x * blockDim.x + threadIdx.x;
    if (idx < LL * BB * HH) { h0[idx] = he[idx]; c0[idx] = ce[idx]; }
    if (idx < BB * DD) {
        int b = idx / DD, k = idx % DD;
        x0[idx] = iseq[(size_t)b * TT * DD + k];
    }
    if (idx < BB) g_fin[idx] = 0;
}

// ---------------- LSTM layer (R10 numerics + register double-buffering) ------
__global__ void k_lstm(const float* __restrict__ xin,
                       const float* __restrict__ hin,
                       const float* __restrict__ cin,
                       float* __restrict__ hout,
                       float* __restrict__ cout,
                       const float* __restrict__ Wih,
                       const float* __restrict__ Whh,
                       const float* __restrict__ bih,
                       const float* __restrict__ bhh,
                       int clearArg)
{
    __shared__ float xs[64][34];
    __shared__ float hs[64][34];
    __shared__ float wis[64][17];
    __shared__ float whs[64][17];
    __shared__ float sg[16][34];

    int tid = threadIdx.x;
    int jbase = blockIdx.x * 4;
    if (clearArg && blockIdx.x == 0 && tid < BB) g_arg[tid] = 0ull;

    int tn = tid & 15;
    int tb = tid >> 4;
    int gate = tn >> 2, jj = tn & 3;
    int row = gate * HH + jbase + jj;

    int wmat = tid >> 7;            // 0 = Wih, 1 = Whh
    int wchk = tid & 127;
    int wr_  = wchk >> 3;           // row 0..15
    int wc_  = wchk & 7;            // chunk 0..7 (8 floats each)
    int wrg = wr_ >> 2, wrj = wr_ & 3;
    int wrow = wrg * HH + jbase + wrj;

    float a1x = 0.f, a1y = 0.f, a2x = 0.f, a2y = 0.f;

    // prefetch registers (double buffer)
    float xr[8], hr[8], wv[8];
#pragma unroll
    for (int i = 0; i < 8; ++i) {
        int idx = tid + 256 * i;
        int k = idx & 63, b = idx >> 6;
        xr[i] = xin[b * DD + k];
        hr[i] = hin[b * HH + k];
    }
    {
        const float* src = (wmat == 0)
            ? &Wih[(size_t)wrow * DD + 8 * wc_]
            : &Whh[(size_t)wrow * HH + 8 * wc_];
        ldg_el8(src, wv);
    }

    for (int kt = 0; kt < DD; kt += 64) {
        __syncthreads();
#pragma unroll
        for (int i = 0; i < 8; ++i) {
            int idx = tid + 256 * i;
            int k = idx & 63, b = idx >> 6;
            xs[k][b] = xr[i];
            hs[k][b] = hr[i];
        }
        {
            float (*dst)[17] = (wmat == 0) ? wis : whs;
#pragma unroll
            for (int j = 0; j < 8; ++j) dst[8 * wc_ + j][wr_] = wv[j];
        }
        __syncthreads();

        if (kt + 64 < DD) {
            int kt2 = kt + 64;
#pragma unroll
            for (int i = 0; i < 8; ++i) {
                int idx = tid + 256 * i;
                int k = idx & 63, b = idx >> 6;
                xr[i] = xin[b * DD + kt2 + k];
                hr[i] = hin[b * HH + kt2 + k];
            }
            const float* src = (wmat == 0)
                ? &Wih[(size_t)wrow * DD + kt2 + 8 * wc_]
                : &Whh[(size_t)wrow * HH + kt2 + 8 * wc_];
            ldg_el8(src, wv);
        }

#pragma unroll 16
        for (int k = 0; k < 64; ++k) {
            float2 xv = *(const float2*)&xs[k][2 * tb];
            float2 hv = *(const float2*)&hs[k][2 * tb];
            float wiv = wis[k][tn];
            float whv = whs[k][tn];
            a1x = __fmaf_rn(xv.x, wiv, a1x);
            a1y = __fmaf_rn(xv.y, wiv, a1y);
            a2x = __fmaf_rn(hv.x, whv, a2x);
            a2y = __fmaf_rn(hv.y, whv, a2y);
        }
    }

    float bi_ = bih[row], bh_ = bhh[row];
    float s0 = __fadd_rn(__fadd_rn(__fadd_rn(a1x, bi_), a2x), bh_);
    float s1 = __fadd_rn(__fadd_rn(__fadd_rn(a1y, bi_), a2y), bh_);
    __syncthreads();
    sg[tn][2 * tb]     = s0;
    sg[tn][2 * tb + 1] = s1;
    __syncthreads();

    if (tid < 128) {
        int b = tid & 31, j2 = tid >> 5;
        float iv = sg[0  + j2][b];
        float fv = sg[4  + j2][b];
        float gv = sg[8  + j2][b];
        float ov = sg[12 + j2][b];
        int j = jbase + j2;
        float si = sigmoid_xla(iv);
        float sf = sigmoid_xla(fv);
        float so = sigmoid_xla(ov);
        float tg = tanh_xla(gv);
        float c2 = __fadd_rn(__fmul_rn(sf, cin[b * HH + j]), __fmul_rn(si, tg));
        float h2 = __fmul_rn(so, tanh_xla(c2));
        cout[b * HH + j] = c2;
        hout[b * HH + j] = h2;
    }
}

// ---------------- logits GEMM: R10 geometry, slimmed inner loop ---------------
// grid 250 x 256. Block: 128 v x 32 b. tn=tid&31 (4 v), tb=tid>>5 (4 b).
// ws read as one LDS.128 (double2); h pre-packed (h,h) as ull in hs2 ->
// inner loop = 3 LDS.128 + 8 FFMA2 (vs R10's 2 LDS.64+1 LDS.128+4 mov+8 FMA2).
// Accumulation chain order identical to R10 -> bit-identical logits.
__global__ void __launch_bounds__(256, 3)
k_logits(const float* __restrict__ hin,
         const float* __restrict__ fcw,
         const float* __restrict__ fcb,
         float* __restrict__ out,
         float* __restrict__ xout,
         const float* __restrict__ embed,
         float* __restrict__ tok_out,
         int t, int has_tok, uint32_t ka, uint32_t kb)
{
    __shared__ float ws[32][132];          // 528B rows (16B-aligned)
    __shared__ ull   hs2[32][34];          // 272B rows (16B-aligned)
    __shared__ int   stok[BB];
    __shared__ unsigned int s_last;

    int tid = threadIdx.x;
    int tn = tid & 31, tb = tid >> 5;
    int vbase = blockIdx.x * 128;

    ull acc01[4], acc23[4];
#pragma unroll
    for (int i = 0; i < 4; ++i) { acc01[i] = 0ull; acc23[i] = 0ull; }

    // fc_w chunk mapping per ktile: 128 n x 4 chunks(8 floats) = 512 = 256t x 2
    float wv8[2][8];
    float4 hr;
    const int pb = tid >> 3, pc = tid & 7;
#pragma unroll
    for (int i = 0; i < 2; ++i) {
        int flat = tid + 256 * i;
        int n = flat >> 2, c = flat & 3;
        ldg_el8(&fcw[(size_t)(vbase + n) * HH + 8 * c], wv8[i]);
    }
    hr = *(const float4*)&hin[pb * HH + 4 * pc];

    for (int kt = 0; kt < HH; kt += 32) {
        __syncthreads();
#pragma unroll
        for (int i = 0; i < 2; ++i) {
            int flat = tid + 256 * i;
            int n = flat >> 2, c = flat & 3;
#pragma unroll
            for (int j = 0; j < 8; ++j) ws[8 * c + j][n] = wv8[i][j];
        }
        hs2[4 * pc + 0][pb] = pk2(hr.x, hr.x);
        hs2[4 * pc + 1][pb] = pk2(hr.y, hr.y);
        hs2[4 * pc + 2][pb] = pk2(hr.z, hr.z);
        hs2[4 * pc + 3][pb] = pk2(hr.w, hr.w);
        __syncthreads();

        if (kt + 32 < HH) {
            int kt2 = kt + 32;
#pragma unroll
            for (int i = 0; i < 2; ++i) {
                int flat = tid + 256 * i;
                int n = flat >> 2, c = flat & 3;
                ldg_el8(&fcw[(size_t)(vbase + n) * HH + kt2 + 8 * c], wv8[i]);
            }
            hr = *(const float4*)&hin[pb * HH + kt2 + 4 * pc];
        }

#pragma unroll
        for (int k = 0; k < 32; ++k) {
            double2 wv = *(const double2*)&ws[k][4 * tn];        // LDS.128
            double2 ha = *(const double2*)&hs2[k][4 * tb];        // LDS.128
            double2 hbq = *(const double2*)&hs2[k][4 * tb + 2];   // LDS.128
            ull wv01 = __double_as_longlong(wv.x);
            ull wv23 = __double_as_longlong(wv.y);
            ull h0 = __double_as_longlong(ha.x);
            ull h1 = __double_as_longlong(ha.y);
            ull h2 = __double_as_longlong(hbq.x);
            ull h3 = __double_as_longlong(hbq.y);
            fma2(acc01[0], h0, wv01); fma2(acc23[0], h0, wv23);
            fma2(acc01[1], h1, wv01); fma2(acc23[1], h1, wv23);
            fma2(acc01[2], h2, wv01); fma2(acc23[2], h2, wv23);
            fma2(acc01[3], h3, wv01); fma2(acc23[3], h3, wv23);
        }
    }

    float4 bv = *(const float4*)&fcb[vbase + 4 * tn];

#pragma unroll
    for (int bi = 0; bi < 4; ++bi) {
        int b = 4 * tb + bi;
        float2 a01 = upk2(acc01[bi]);
        float2 a23 = upk2(acc23[bi]);
        float4 lg;
        lg.x = __fadd_rn(a01.x, bv.x);
        lg.y = __fadd_rn(a01.y, bv.y);
        lg.z = __fadd_rn(a23.x, bv.z);
        lg.w = __fadd_rn(a23.y, bv.w);
        __stcs((float4*)&out[((size_t)b * TT + t) * VV + vbase + 4 * tn], lg);

        unsigned long long best = 0ull;
        float lgs[4] = {lg.x, lg.y, lg.z, lg.w};
#pragma unroll
        for (int ni = 0; ni < 4; ++ni) {
            int v = vbase + 4 * tn + ni;
            uint32_t i = (uint32_t)(b * VV + v);
            uint32_t o0, o1;
            threefry2x32(ka, kb, 0u, i, o0, o1);
            uint32_t bits = o0 ^ o1;
            float f = __uint_as_float((bits >> 9) | 0x3f800000u) - 1.0f;
            float u = fmaxf(1.17549435e-38f, f);
            float g = -logf(-logf(u));
            float val = __fadd_rn(lgs[ni], g);
            uint32_t ub = __float_as_uint(val);
            ub = (ub & 0x80000000u) ? ~ub : (ub | 0x80000000u);
            unsigned long long key = ((unsigned long long)ub << 32) |
                (unsigned long long)(0x7fffffffu - (uint32_t)v);
            if (key > best) best = key;
        }
#pragma unroll
        for (int o = 16; o; o >>= 1) {
            unsigned long long other = __shfl_down_sync(0xffffffffu, best, o);
            if (other > best) best = other;
        }
        if (tn == 0) atomicMax(&g_arg[b], best);
    }

    // ---- fused sampler: last block to finish does token select + embed gather
    __threadfence();
    if (tid == 0) {
        unsigned int total = gridDim.x * gridDim.y;
        unsigned int v = atomicAdd(&g_tick, 1u);
        s_last = (v == total - 1u) ? 1u : 0u;
    }
    __syncthreads();
    if (s_last) {
        if (tid == 0) g_tick = 0u;
        __threadfence();
        if (tid < BB) {
            unsigned long long key = g_arg[tid];
            int sampled = 0x7fffffff - (int)(uint32_t)(key & 0xffffffffu);
            int fin = g_fin[tid];
            int token = fin ? PAD_TOK : sampled;
            g_fin[tid] = fin | (sampled == EOS_TOK);
            stok[tid] = token;
            if (has_tok) tok_out[(size_t)tid * TT + t] = (float)token;
        }
        __syncthreads();
        for (int i = tid; i < BB * DD / 4; i += 256) {
            int b = i >> 7;
            int c = i & 127;
            ((float4*)xout)[b * 128 + c] =
                ((const float4*)embed)[(size_t)stok[b] * 128 + c];
        }
    }
}

// ---------------- host launch --------------------------------------------------
extern "C" void kernel_launch(void* const* d_in, const int* in_sizes, int n_in,
                              void* d_out, int out_size)
{
    const float* input_seq = (const float*)d_in[0];
    const float* h_enc     = (const float*)d_in[1];
    const float* c_enc     = (const float*)d_in[2];
    const float* W_ih      = (const float*)d_in[3];
    const float* W_hh      = (const float*)d_in[4];
    const float* b_ih      = (const float*)d_in[5];
    const float* b_hh      = (const float*)d_in[6];
    const float* fc_w      = (const float*)d_in[7];
    const float* fc_b      = (const float*)d_in[8];
    const float* embed     = (const float*)d_in[9];
    float* out = (float*)d_out;

    long long need_tok = (long long)BB * TT * VV + (long long)BB * TT;
    int has_tok = ((long long)out_size >= need_tok) ? 1 : 0;
    float* tok_out = out + (size_t)BB * TT * VV;

    float *hb, *cb, *xb;
    cudaGetSymbolAddress((void**)&hb, g_h);
    cudaGetSymbolAddress((void**)&cb, g_c);
    cudaGetSymbolAddress((void**)&xb, g_x);
#define HP(p, lyr) (hb + (((p) * LL) + (lyr)) * (BB * HH))
#define CP(p, lyr) (cb + (((p) * LL) + (lyr)) * (BB * HH))
#define XP(p)      (xb + (p) * (BB * DD))

    k_init<<<64, 512>>>(input_seq, h_enc, c_enc, HP(0, 0), CP(0, 0), XP(0));

    for (int t = 0; t < TT; ++t) {
        int p = t & 1, q = p ^ 1;

        k_lstm<<<128, 256>>>(XP(p), HP(p, 0), CP(p, 0),
                             HP(q, 0), CP(q, 0),
                             W_ih, W_hh, b_ih, b_hh, /*clearArg=*/1);
        k_lstm<<<128, 256>>>(HP(q, 0), HP(p, 1), CP(p, 1),
                             HP(q, 1), CP(q, 1),
                             W_ih + (size_t)G4 * DD,
                             W_hh + (size_t)G4 * HH,
                             b_ih + G4, b_hh + G4, /*clearArg=*/0);

        uint32_t ka, kb;
        threefry2x32(0u, 42u, 0u, (uint32_t)t, ka, kb);

        k_logits<<<250, 256>>>(HP(q, 1), fc_w, fc_b, out,
                               XP(q), embed, tok_out, t, has_tok, ka, kb);
    }
#undef HP
#undef CP
#undef XP
}

// round 14
// speedup vs baseline: 1.4787x; 1.0047x over previous
#include <cuda_runtime.h>
#include <cstdint>
#include <cstddef>

#define BB 32
#define TT 64
#define DD 512
#define HH 512
#define VV 32000
#define LL 2
#define G4 2048           // 4*H
#define EOS_TOK 3
#define PAD_TOK 0

typedef unsigned long long ull;

// ---------------- persistent device state (no allocations allowed) ----------
__device__ float g_h[2][LL][BB][HH];   // parity ping-pong
__device__ float g_c[2][LL][BB][HH];
__device__ float g_x[2][BB][DD];
__device__ int   g_fin[BB];
__device__ unsigned long long g_arg[BB];
__device__ unsigned int g_tick;        // sampler ticket (reset by sampler)

// ---------------- 32-byte L2::evict_last load (sm_100a requires v8.b32) ------
__device__ __forceinline__ void ldg_el8(const float* __restrict__ p, float* v) {
    uint32_t r0, r1, r2, r3, r4, r5, r6, r7;
    asm volatile(
        "ld.global.nc.L2::evict_last.v8.b32 {%0,%1,%2,%3,%4,%5,%6,%7}, [%8];"
        : "=r"(r0), "=r"(r1), "=r"(r2), "=r"(r3),
          "=r"(r4), "=r"(r5), "=r"(r6), "=r"(r7)
        : "l"(p));
    v[0] = __uint_as_float(r0); v[1] = __uint_as_float(r1);
    v[2] = __uint_as_float(r2); v[3] = __uint_as_float(r3);
    v[4] = __uint_as_float(r4); v[5] = __uint_as_float(r5);
    v[6] = __uint_as_float(r6); v[7] = __uint_as_float(r7);
}

// ---------------- packed f32x2 helpers (sm_100a full-rate fp32) -------------
__device__ __forceinline__ ull pk2(float lo, float hi) {
    ull r; asm("mov.b64 %0, {%1, %2};" : "=l"(r) : "f"(lo), "f"(hi)); return r;
}
__device__ __forceinline__ void fma2(ull& d, ull a, ull b) {
    asm("fma.rn.f32x2 %0, %1, %2, %3;" : "=l"(d) : "l"(a), "l"(b), "l"(d));
}
__device__ __forceinline__ float2 upk2(ull v) {
    float2 f; asm("mov.b64 {%0, %1}, %2;" : "=f"(f.x), "=f"(f.y) : "l"(v)); return f;
}

// ---------------- XLA-exact f32 tanh (Eigen-style rational, fma chain) ------
__device__ __forceinline__ float tanh_xla(float x) {
    const float kClamp = 7.90531110763549805f;
    float xc = fminf(fmaxf(x, -kClamp), kClamp);
    float x2 = __fmul_rn(xc, xc);
    float p = __fmaf_rn(x2, -2.76076847742355e-16f, 2.00018790482477e-13f);
    p = __fmaf_rn(x2, p, -8.60467152213735e-11f);
    p = __fmaf_rn(x2, p,  5.12229709037114e-08f);
    p = __fmaf_rn(x2, p,  1.48572235717979e-05f);
    p = __fmaf_rn(x2, p,  6.37261928875436e-04f);
    p = __fmaf_rn(x2, p,  4.89352455891786e-03f);
    p = __fmul_rn(xc, p);
    float q = __fmaf_rn(x2, 1.19825839466702e-06f, 1.18534705686654e-04f);
    q = __fmaf_rn(x2, q, 2.26843463243900e-03f);
    q = __fmaf_rn(x2, q, 4.89352518554385e-03f);
    float r = __fdiv_rn(p, q);
    return (fabsf(x) < 0.0004f) ? x : r;
}

__device__ __forceinline__ float sigmoid_xla(float x) {
    float t = tanh_xla(__fmul_rn(0.5f, x));
    return __fadd_rn(0.5f, __fmul_rn(0.5f, t));
}

// ---------------- threefry2x32 (JAX-exact) ----------------------------------
__host__ __device__ __forceinline__ uint32_t rotl32(uint32_t v, int r) {
    return (v << r) | (v >> (32 - r));
}

__host__ __device__ __forceinline__ void threefry2x32(
    uint32_t k0, uint32_t k1, uint32_t x0, uint32_t x1,
    uint32_t& o0, uint32_t& o1)
{
    uint32_t ks2 = k0 ^ k1 ^ 0x1BD11BDAu;
    x0 += k0; x1 += k1;
#define TF_G(r0,r1,r2,r3,a0,a1)                         \
    x0 += x1; x1 = rotl32(x1, r0); x1 ^= x0;            \
    x0 += x1; x1 = rotl32(x1, r1); x1 ^= x0;            \
    x0 += x1; x1 = rotl32(x1, r2); x1 ^= x0;            \
    x0 += x1; x1 = rotl32(x1, r3); x1 ^= x0;            \
    x0 += (a0); x1 += (a1);
    TF_G(13, 15, 26,  6, k1,  ks2 + 1u)
    TF_G(17, 29, 16, 24, ks2, k0  + 2u)
    TF_G(13, 15, 26,  6, k0,  k1  + 3u)
    TF_G(17, 29, 16, 24, k1,  ks2 + 4u)
    TF_G(13, 15, 26,  6, ks2, k0  + 5u)
#undef TF_G
    o0 = x0; o1 = x1;
}

// ---------------- init ---------------------------------------------------------
__global__ void k_init(const float* __restrict__ iseq,
                       const float* __restrict__ he,
                       const float* __restrict__ ce,
                       float* __restrict__ h0, float* __restrict__ c0,
                       float* __restrict__ x0)
{
    int idx = blockIdx.x * blockDim.x + threadIdx.x;
    if (idx < LL * BB * HH) { h0[idx] = he[idx]; c0[idx] = ce[idx]; }
    if (idx < BB * DD) {
        int b = idx / DD, k = idx % DD;
        x0[idx] = iseq[(size_t)b * TT * DD + k];
    }
    if (idx < BB) g_fin[idx] = 0;
}

// ---------------- LSTM layer (R13 proven: depth-1 register double-buffer) ----
__global__ void k_lstm(const float* __restrict__ xin,
                       const float* __restrict__ hin,
                       const float* __restrict__ cin,
                       float* __restrict__ hout,
                       float* __restrict__ cout,
                       const float* __restrict__ Wih,
                       const float* __restrict__ Whh,
                       const float* __restrict__ bih,
                       const float* __restrict__ bhh,
                       int clearArg)
{
    __shared__ float xs[64][34];
    __shared__ float hs[64][34];
    __shared__ float wis[64][17];
    __shared__ float whs[64][17];
    __shared__ float sg[16][34];

    int tid = threadIdx.x;
    int jbase = blockIdx.x * 4;
    if (clearArg && blockIdx.x == 0 && tid < BB) g_arg[tid] = 0ull;

    int tn = tid & 15;
    int tb = tid >> 4;
    int gate = tn >> 2, jj = tn & 3;
    int row = gate * HH + jbase + jj;

    int wmat = tid >> 7;            // 0 = Wih, 1 = Whh
    int wchk = tid & 127;
    int wr_  = wchk >> 3;           // row 0..15
    int wc_  = wchk & 7;            // chunk 0..7 (8 floats each)
    int wrg = wr_ >> 2, wrj = wr_ & 3;
    int wrow = wrg * HH + jbase + wrj;

    float a1x = 0.f, a1y = 0.f, a2x = 0.f, a2y = 0.f;

    float xr[8], hr[8], wv[8];
#pragma unroll
    for (int i = 0; i < 8; ++i) {
        int idx = tid + 256 * i;
        int k = idx & 63, b = idx >> 6;
        xr[i] = xin[b * DD + k];
        hr[i] = hin[b * HH + k];
    }
    {
        const float* src = (wmat == 0)
            ? &Wih[(size_t)wrow * DD + 8 * wc_]
            : &Whh[(size_t)wrow * HH + 8 * wc_];
        ldg_el8(src, wv);
    }

    for (int kt = 0; kt < DD; kt += 64) {
        __syncthreads();
#pragma unroll
        for (int i = 0; i < 8; ++i) {
            int idx = tid + 256 * i;
            int k = idx & 63, b = idx >> 6;
            xs[k][b] = xr[i];
            hs[k][b] = hr[i];
        }
        {
            float (*dst)[17] = (wmat == 0) ? wis : whs;
#pragma unroll
            for (int j = 0; j < 8; ++j) dst[8 * wc_ + j][wr_] = wv[j];
        }
        __syncthreads();

        if (kt + 64 < DD) {
            int kt2 = kt + 64;
#pragma unroll
            for (int i = 0; i < 8; ++i) {
                int idx = tid + 256 * i;
                int k = idx & 63, b = idx >> 6;
                xr[i] = xin[b * DD + kt2 + k];
                hr[i] = hin[b * HH + kt2 + k];
            }
            const float* src = (wmat == 0)
                ? &Wih[(size_t)wrow * DD + kt2 + 8 * wc_]
                : &Whh[(size_t)wrow * HH + kt2 + 8 * wc_];
            ldg_el8(src, wv);
        }

#pragma unroll 16
        for (int k = 0; k < 64; ++k) {
            float2 xv = *(const float2*)&xs[k][2 * tb];
            float2 hv = *(const float2*)&hs[k][2 * tb];
            float wiv = wis[k][tn];
            float whv = whs[k][tn];
            a1x = __fmaf_rn(xv.x, wiv, a1x);
            a1y = __fmaf_rn(xv.y, wiv, a1y);
            a2x = __fmaf_rn(hv.x, whv, a2x);
            a2y = __fmaf_rn(hv.y, whv, a2y);
        }
    }

    float bi_ = bih[row], bh_ = bhh[row];
    float s0 = __fadd_rn(__fadd_rn(__fadd_rn(a1x, bi_), a2x), bh_);
    float s1 = __fadd_rn(__fadd_rn(__fadd_rn(a1y, bi_), a2y), bh_);
    __syncthreads();
    sg[tn][2 * tb]     = s0;
    sg[tn][2 * tb + 1] = s1;
    __syncthreads();

    if (tid < 128) {
        int b = tid & 31, j2 = tid >> 5;
        float iv = sg[0  + j2][b];
        float fv = sg[4  + j2][b];
        float gv = sg[8  + j2][b];
        float ov = sg[12 + j2][b];
        int j = jbase + j2;
        float si = sigmoid_xla(iv);
        float sf = sigmoid_xla(fv);
        float so = sigmoid_xla(ov);
        float tg = tanh_xla(gv);
        float c2 = __fadd_rn(__fmul_rn(sf, cin[b * HH + j]), __fmul_rn(si, tg));
        float h2 = __fmul_rn(so, tanh_xla(c2));
        cout[b * HH + j] = c2;
        hout[b * HH + j] = h2;
    }
}

// ---------------- logits GEMM: R13 inner loop + DEPTH-2 register prefetch -----
// grid 250 x 256. Block: 128 v x 32 b. tn=tid&31 (4 v), tb=tid>>5 (4 b).
// Loads for ktile i+2 issued at tile i -> ~2 tile-times (>800 cyc) to cover
// DRAM latency. Two parity register buffers. Chains bit-identical to R13.
__global__ void __launch_bounds__(256, 2)
k_logits(const float* __restrict__ hin,
         const float* __restrict__ fcw,
         const float* __restrict__ fcb,
         float* __restrict__ out,
         float* __restrict__ xout,
         const float* __restrict__ embed,
         float* __restrict__ tok_out,
         int t, int has_tok, uint32_t ka, uint32_t kb)
{
    __shared__ float ws[32][132];          // 528B rows (16B-aligned)
    __shared__ ull   hs2[32][34];          // 272B rows (16B-aligned)
    __shared__ int   stok[BB];
    __shared__ unsigned int s_last;

    int tid = threadIdx.x;
    int tn = tid & 31, tb = tid >> 5;
    int vbase = blockIdx.x * 128;

    ull acc01[4], acc23[4];
#pragma unroll
    for (int i = 0; i < 4; ++i) { acc01[i] = 0ull; acc23[i] = 0ull; }

    // fc_w chunk mapping per ktile: 128 n x 4 chunks(8 floats) = 512 = 256t x 2
    const int wn0 = tid >> 2,           wc0 = tid & 3;          // chunk 0
    const int wn1 = (tid + 256) >> 2,   wc1 = (tid + 256) & 3;  // chunk 1
    const int pb = tid >> 3, pc = tid & 7;

    // depth-2 prefetch: parity register buffers for ktiles i and i+1
    float wv8[2][2][8];
    float4 hr[2];
#pragma unroll
    for (int p = 0; p < 2; ++p) {
        int kt = 32 * p;
        ldg_el8(&fcw[(size_t)(vbase + wn0) * HH + kt + 8 * wc0], wv8[p][0]);
        ldg_el8(&fcw[(size_t)(vbase + wn1) * HH + kt + 8 * wc1], wv8[p][1]);
        hr[p] = *(const float4*)&hin[pb * HH + kt + 4 * pc];
    }

#pragma unroll 2
    for (int it = 0; it < 16; ++it) {
        const int par = it & 1;
        __syncthreads();
        {
#pragma unroll
            for (int j = 0; j < 8; ++j) ws[8 * wc0 + j][wn0] = wv8[par][0][j];
#pragma unroll
            for (int j = 0; j < 8; ++j) ws[8 * wc1 + j][wn1] = wv8[par][1][j];
            hs2[4 * pc + 0][pb] = pk2(hr[par].x, hr[par].x);
            hs2[4 * pc + 1][pb] = pk2(hr[par].y, hr[par].y);
            hs2[4 * pc + 2][pb] = pk2(hr[par].z, hr[par].z);
            hs2[4 * pc + 3][pb] = pk2(hr[par].w, hr[par].w);
        }
        __syncthreads();

        if (it + 2 < 16) {
            int kt2 = 32 * (it + 2);
            ldg_el8(&fcw[(size_t)(vbase + wn0) * HH + kt2 + 8 * wc0], wv8[par][0]);
            ldg_el8(&fcw[(size_t)(vbase + wn1) * HH + kt2 + 8 * wc1], wv8[par][1]);
            hr[par] = *(const float4*)&hin[pb * HH + kt2 + 4 * pc];
        }

#pragma unroll
        for (int k = 0; k < 32; ++k) {
            double2 wv = *(const double2*)&ws[k][4 * tn];         // LDS.128
            double2 ha = *(const double2*)&hs2[k][4 * tb];        // LDS.128
            double2 hbq = *(const double2*)&hs2[k][4 * tb + 2];   // LDS.128
            ull wv01 = __double_as_longlong(wv.x);
            ull wv23 = __double_as_longlong(wv.y);
            ull h0 = __double_as_longlong(ha.x);
            ull h1 = __double_as_longlong(ha.y);
            ull h2 = __double_as_longlong(hbq.x);
            ull h3 = __double_as_longlong(hbq.y);
            fma2(acc01[0], h0, wv01); fma2(acc23[0], h0, wv23);
            fma2(acc01[1], h1, wv01); fma2(acc23[1], h1, wv23);
            fma2(acc01[2], h2, wv01); fma2(acc23[2], h2, wv23);
            fma2(acc01[3], h3, wv01); fma2(acc23[3], h3, wv23);
        }
    }

    float4 bv = *(const float4*)&fcb[vbase + 4 * tn];

#pragma unroll
    for (int bi = 0; bi < 4; ++bi) {
        int b = 4 * tb + bi;
        float2 a01 = upk2(acc01[bi]);
        float2 a23 = upk2(acc23[bi]);
        float4 lg;
        lg.x = __fadd_rn(a01.x, bv.x);
        lg.y = __fadd_rn(a01.y, bv.y);
        lg.z = __fadd_rn(a23.x, bv.z);
        lg.w = __fadd_rn(a23.y, bv.w);
        __stcs((float4*)&out[((size_t)b * TT + t) * VV + vbase + 4 * tn], lg);

        unsigned long long best = 0ull;
        float lgs[4] = {lg.x, lg.y, lg.z, lg.w};
#pragma unroll
        for (int ni = 0; ni < 4; ++ni) {
            int v = vbase + 4 * tn + ni;
            uint32_t i = (uint32_t)(b * VV + v);
            uint32_t o0, o1;
            threefry2x32(ka, kb, 0u, i, o0, o1);
            uint32_t bits = o0 ^ o1;
            float f = __uint_as_float((bits >> 9) | 0x3f800000u) - 1.0f;
            float u = fmaxf(1.17549435e-38f, f);
            float g = -logf(-logf(u));
            float val = __fadd_rn(lgs[ni], g);
            uint32_t ub = __float_as_uint(val);
            ub = (ub & 0x80000000u) ? ~ub : (ub | 0x80000000u);
            unsigned long long key = ((unsigned long long)ub << 32) |
                (unsigned long long)(0x7fffffffu - (uint32_t)v);
            if (key > best) best = key;
        }
#pragma unroll
        for (int o = 16; o; o >>= 1) {
            unsigned long long other = __shfl_down_sync(0xffffffffu, best, o);
            if (other > best) best = other;
        }
        if (tn == 0) atomicMax(&g_arg[b], best);
    }

    // ---- fused sampler: last block to finish does token select + embed gather
    __threadfence();
    if (tid == 0) {
        unsigned int total = gridDim.x * gridDim.y;
        unsigned int v = atomicAdd(&g_tick, 1u);
        s_last = (v == total - 1u) ? 1u : 0u;
    }
    __syncthreads();
    if (s_last) {
        if (tid == 0) g_tick = 0u;
        __threadfence();
        if (tid < BB) {
            unsigned long long key = g_arg[tid];
            int sampled = 0x7fffffff - (int)(uint32_t)(key & 0xffffffffu);
            int fin = g_fin[tid];
            int token = fin ? PAD_TOK : sampled;
            g_fin[tid] = fin | (sampled == EOS_TOK);
            stok[tid] = token;
            if (has_tok) tok_out[(size_t)tid * TT + t] = (float)token;
        }
        __syncthreads();
        for (int i = tid; i < BB * DD / 4; i += 256) {
            int b = i >> 7;
            int c = i & 127;
            ((float4*)xout)[b * 128 + c] =
                ((const float4*)embed)[(size_t)stok[b] * 128 + c];
        }
    }
}

// ---------------- host launch --------------------------------------------------
extern "C" void kernel_launch(void* const* d_in, const int* in_sizes, int n_in,
                              void* d_out, int out_size)
{
    const float* input_seq = (const float*)d_in[0];
    const float* h_enc     = (const float*)d_in[1];
    const float* c_enc     = (const float*)d_in[2];
    const float* W_ih      = (const float*)d_in[3];
    const float* W_hh      = (const float*)d_in[4];
    const float* b_ih      = (const float*)d_in[5];
    const float* b_hh      = (const float*)d_in[6];
    const float* fc_w      = (const float*)d_in[7];
    const float* fc_b      = (const float*)d_in[8];
    const float* embed     = (const float*)d_in[9];
    float* out = (float*)d_out;

    long long need_tok = (long long)BB * TT * VV + (long long)BB * TT;
    int has_tok = ((long long)out_size >= need_tok) ? 1 : 0;
    float* tok_out = out + (size_t)BB * TT * VV;

    float *hb, *cb, *xb;
    cudaGetSymbolAddress((void**)&hb, g_h);
    cudaGetSymbolAddress((void**)&cb, g_c);
    cudaGetSymbolAddress((void**)&xb, g_x);
#define HP(p, lyr) (hb + (((p) * LL) + (lyr)) * (BB * HH))
#define CP(p, lyr) (cb + (((p) * LL) + (lyr)) * (BB * HH))
#define XP(p)      (xb + (p) * (BB * DD))

    k_init<<<64, 512>>>(input_seq, h_enc, c_enc, HP(0, 0), CP(0, 0), XP(0));

    for (int t = 0; t < TT; ++t) {
        int p = t & 1, q = p ^ 1;

        k_lstm<<<128, 256>>>(XP(p), HP(p, 0), CP(p, 0),
                             HP(q, 0), CP(q, 0),
                             W_ih, W_hh, b_ih, b_hh, /*clearArg=*/1);
        k_lstm<<<128, 256>>>(HP(q, 0), HP(p, 1), CP(p, 1),
                             HP(q, 1), CP(q, 1),
                             W_ih + (size_t)G4 * DD,
                             W_hh + (size_t)G4 * HH,
                             b_ih + G4, b_hh + G4, /*clearArg=*/0);

        uint32_t ka, kb;
        threefry2x32(0u, 42u, 0u, (uint32_t)t, ka, kb);

        k_logits<<<250, 256>>>(HP(q, 1), fc_w, fc_b, out,
                               XP(q), embed, tok_out, t, has_tok, ka, kb);
    }
#undef HP
#undef CP
#undef XP
}

// round 15
// speedup vs baseline: 1.6577x; 1.1211x over previous
#include <cuda_runtime.h>
#include <cstdint>
#include <cstddef>

#define BB 32
#define TT 64
#define DD 512
#define HH 512
#define VV 32000
#define LL 2
#define G4 2048           // 4*H
#define EOS_TOK 3
#define PAD_TOK 0

typedef unsigned long long ull;

// ---------------- persistent device state (no allocations allowed) ----------
__device__ float g_h[2][LL][BB][HH];   // parity ping-pong
__device__ float g_c[2][LL][BB][HH];
__device__ float g_x[2][BB][DD];
__device__ int   g_fin[BB];
__device__ unsigned long long g_arg[BB];
__device__ unsigned int g_tick;        // sampler ticket (reset by sampler)

// ---------------- 32-byte L2::evict_last load (sm_100a requires v8.b32) ------
__device__ __forceinline__ void ldg_el8(const float* __restrict__ p, float* v) {
    uint32_t r0, r1, r2, r3, r4, r5, r6, r7;
    asm volatile(
        "ld.global.nc.L2::evict_last.v8.b32 {%0,%1,%2,%3,%4,%5,%6,%7}, [%8];"
        : "=r"(r0), "=r"(r1), "=r"(r2), "=r"(r3),
          "=r"(r4), "=r"(r5), "=r"(r6), "=r"(r7)
        : "l"(p));
    v[0] = __uint_as_float(r0); v[1] = __uint_as_float(r1);
    v[2] = __uint_as_float(r2); v[3] = __uint_as_float(r3);
    v[4] = __uint_as_float(r4); v[5] = __uint_as_float(r5);
    v[6] = __uint_as_float(r6); v[7] = __uint_as_float(r7);
}

// ---------------- packed f32x2 helpers (sm_100a full-rate fp32) -------------
__device__ __forceinline__ ull pk2(float lo, float hi) {
    ull r; asm("mov.b64 %0, {%1, %2};" : "=l"(r) : "f"(lo), "f"(hi)); return r;
}
__device__ __forceinline__ void fma2(ull& d, ull a, ull b) {
    asm("fma.rn.f32x2 %0, %1, %2, %3;" : "=l"(d) : "l"(a), "l"(b), "l"(d));
}
__device__ __forceinline__ float2 upk2(ull v) {
    float2 f; asm("mov.b64 {%0, %1}, %2;" : "=f"(f.x), "=f"(f.y) : "l"(v)); return f;
}

// ---------------- XLA-exact f32 tanh (Eigen-style rational, fma chain) ------
__device__ __forceinline__ float tanh_xla(float x) {
    const float kClamp = 7.90531110763549805f;
    float xc = fminf(fmaxf(x, -kClamp), kClamp);
    float x2 = __fmul_rn(xc, xc);
    float p = __fmaf_rn(x2, -2.76076847742355e-16f, 2.00018790482477e-13f);
    p = __fmaf_rn(x2, p, -8.60467152213735e-11f);
    p = __fmaf_rn(x2, p,  5.12229709037114e-08f);
    p = __fmaf_rn(x2, p,  1.48572235717979e-05f);
    p = __fmaf_rn(x2, p,  6.37261928875436e-04f);
    p = __fmaf_rn(x2, p,  4.89352455891786e-03f);
    p = __fmul_rn(xc, p);
    float q = __fmaf_rn(x2, 1.19825839466702e-06f, 1.18534705686654e-04f);
    q = __fmaf_rn(x2, q, 2.26843463243900e-03f);
    q = __fmaf_rn(x2, q, 4.89352518554385e-03f);
    float r = __fdiv_rn(p, q);
    return (fabsf(x) < 0.0004f) ? x : r;
}

__device__ __forceinline__ float sigmoid_xla(float x) {
    float t = tanh_xla(__fmul_rn(0.5f, x));
    return __fadd_rn(0.5f, __fmul_rn(0.5f, t));
}

// ---------------- threefry2x32 (JAX-exact) ----------------------------------
__host__ __device__ __forceinline__ uint32_t rotl32(uint32_t v, int r) {
    return (v << r) | (v >> (32 - r));
}

__host__ __device__ __forceinline__ void threefry2x32(
    uint32_t k0, uint32_t k1, uint32_t x0, uint32_t x1,
    uint32_t& o0, uint32_t& o1)
{
    uint32_t ks2 = k0 ^ k1 ^ 0x1BD11BDAu;
    x0 += k0; x1 += k1;
#define TF_G(r0,r1,r2,r3,a0,a1)                         \
    x0 += x1; x1 = rotl32(x1, r0); x1 ^= x0;            \
    x0 += x1; x1 = rotl32(x1, r1); x1 ^= x0;            \
    x0 += x1; x1 = rotl32(x1, r2); x1 ^= x0;            \
    x0 += x1; x1 = rotl32(x1, r3); x1 ^= x0;            \
    x0 += (a0); x1 += (a1);
    TF_G(13, 15, 26,  6, k1,  ks2 + 1u)
    TF_G(17, 29, 16, 24, ks2, k0  + 2u)
    TF_G(13, 15, 26,  6, k0,  k1  + 3u)
    TF_G(17, 29, 16, 24, k1,  ks2 + 4u)
    TF_G(13, 15, 26,  6, ks2, k0  + 5u)
#undef TF_G
    o0 = x0; o1 = x1;
}

// ---------------- init ---------------------------------------------------------
__global__ void k_init(const float* __restrict__ iseq,
                       const float* __restrict__ he,
                       const float* __restrict__ ce,
                       float* __restrict__ h0, float* __restrict__ c0,
                       float* __restrict__ x0)
{
    int idx = blockIdx.x * blockDim.x + threadIdx.x;
    if (idx < LL * BB * HH) { h0[idx] = he[idx]; c0[idx] = ce[idx]; }
    if (idx < BB * DD) {
        int b = idx / DD, k = idx % DD;
        x0[idx] = iseq[(size_t)b * TT * DD + k];
    }
    if (idx < BB) g_fin[idx] = 0;
}

// ---------------- LSTM layer (R13 proven: depth-1 register double-buffer) ----
__global__ void k_lstm(const float* __restrict__ xin,
                       const float* __restrict__ hin,
                       const float* __restrict__ cin,
                       float* __restrict__ hout,
                       float* __restrict__ cout,
                       const float* __restrict__ Wih,
                       const float* __restrict__ Whh,
                       const float* __restrict__ bih,
                       const float* __restrict__ bhh,
                       int clearArg)
{
    __shared__ float xs[64][34];
    __shared__ float hs[64][34];
    __shared__ float wis[64][17];
    __shared__ float whs[64][17];
    __shared__ float sg[16][34];

    int tid = threadIdx.x;
    int jbase = blockIdx.x * 4;
    if (clearArg && blockIdx.x == 0 && tid < BB) g_arg[tid] = 0ull;

    int tn = tid & 15;
    int tb = tid >> 4;
    int gate = tn >> 2, jj = tn & 3;
    int row = gate * HH + jbase + jj;

    int wmat = tid >> 7;            // 0 = Wih, 1 = Whh
    int wchk = tid & 127;
    int wr_  = wchk >> 3;           // row 0..15
    int wc_  = wchk & 7;            // chunk 0..7 (8 floats each)
    int wrg = wr_ >> 2, wrj = wr_ & 3;
    int wrow = wrg * HH + jbase + wrj;

    float a1x = 0.f, a1y = 0.f, a2x = 0.f, a2y = 0.f;

    float xr[8], hr[8], wv[8];
#pragma unroll
    for (int i = 0; i < 8; ++i) {
        int idx = tid + 256 * i;
        int k = idx & 63, b = idx >> 6;
        xr[i] = xin[b * DD + k];
        hr[i] = hin[b * HH + k];
    }
    {
        const float* src = (wmat == 0)
            ? &Wih[(size_t)wrow * DD + 8 * wc_]
            : &Whh[(size_t)wrow * HH + 8 * wc_];
        ldg_el8(src, wv);
    }

    for (int kt = 0; kt < DD; kt += 64) {
        __syncthreads();
#pragma unroll
        for (int i = 0; i < 8; ++i) {
            int idx = tid + 256 * i;
            int k = idx & 63, b = idx >> 6;
            xs[k][b] = xr[i];
            hs[k][b] = hr[i];
        }
        {
            float (*dst)[17] = (wmat == 0) ? wis : whs;
#pragma unroll
            for (int j = 0; j < 8; ++j) dst[8 * wc_ + j][wr_] = wv[j];
        }
        __syncthreads();

        if (kt + 64 < DD) {
            int kt2 = kt + 64;
#pragma unroll
            for (int i = 0; i < 8; ++i) {
                int idx = tid + 256 * i;
                int k = idx & 63, b = idx >> 6;
                xr[i] = xin[b * DD + kt2 + k];
                hr[i] = hin[b * HH + kt2 + k];
            }
            const float* src = (wmat == 0)
                ? &Wih[(size_t)wrow * DD + kt2 + 8 * wc_]
                : &Whh[(size_t)wrow * HH + kt2 + 8 * wc_];
            ldg_el8(src, wv);
        }

#pragma unroll 16
        for (int k = 0; k < 64; ++k) {
            float2 xv = *(const float2*)&xs[k][2 * tb];
            float2 hv = *(const float2*)&hs[k][2 * tb];
            float wiv = wis[k][tn];
            float whv = whs[k][tn];
            a1x = __fmaf_rn(xv.x, wiv, a1x);
            a1y = __fmaf_rn(xv.y, wiv, a1y);
            a2x = __fmaf_rn(hv.x, whv, a2x);
            a2y = __fmaf_rn(hv.y, whv, a2y);
        }
    }

    float bi_ = bih[row], bh_ = bhh[row];
    float s0 = __fadd_rn(__fadd_rn(__fadd_rn(a1x, bi_), a2x), bh_);
    float s1 = __fadd_rn(__fadd_rn(__fadd_rn(a1y, bi_), a2y), bh_);
    __syncthreads();
    sg[tn][2 * tb]     = s0;
    sg[tn][2 * tb + 1] = s1;
    __syncthreads();

    if (tid < 128) {
        int b = tid & 31, j2 = tid >> 5;
        float iv = sg[0  + j2][b];
        float fv = sg[4  + j2][b];
        float gv = sg[8  + j2][b];
        float ov = sg[12 + j2][b];
        int j = jbase + j2;
        float si = sigmoid_xla(iv);
        float sf = sigmoid_xla(fv);
        float so = sigmoid_xla(ov);
        float tg = tanh_xla(gv);
        float c2 = __fadd_rn(__fmul_rn(sf, cin[b * HH + j]), __fmul_rn(si, tg));
        float h2 = __fmul_rn(so, tanh_xla(c2));
        cout[b * HH + j] = c2;
        hout[b * HH + j] = h2;
    }
}

// ---------------- logits GEMM: R10 verbatim (measured 60.1 us) -----------------
// grid 250 x 256. Block: 128 v x 32 b. tn=tid&31 (4 v), tb=tid>>5 (4 b).
// fc_w: 2x v8.b32 evict_last loads/thread/ktile. depth-1 register prefetch.
// Inner loop: 2x LDS.64 (ws) + 1x LDS.128 (hs) + 4x pk2 + 8x FFMA2.
// logits: __stcs evict-first. Chains bit-identical to all passing rounds.
__global__ void __launch_bounds__(256, 3)
k_logits(const float* __restrict__ hin,
         const float* __restrict__ fcw,
         const float* __restrict__ fcb,
         float* __restrict__ out,
         float* __restrict__ xout,
         const float* __restrict__ embed,
         float* __restrict__ tok_out,
         int t, int has_tok, uint32_t ka, uint32_t kb)
{
    __shared__ float ws[32][132];
    __shared__ float hs[32][36];
    __shared__ int   stok[BB];
    __shared__ unsigned int s_last;

    int tid = threadIdx.x;
    int tn = tid & 31, tb = tid >> 5;
    int vbase = blockIdx.x * 128;

    ull acc01[4], acc23[4];
#pragma unroll
    for (int i = 0; i < 4; ++i) { acc01[i] = 0ull; acc23[i] = 0ull; }

    // fc_w chunk mapping per ktile: 128 n x 4 chunks(8 floats) = 512 = 256t x 2
    float wv8[2][8];
    float4 hr;
    const int pb = tid >> 3, pc = tid & 7;
#pragma unroll
    for (int i = 0; i < 2; ++i) {
        int flat = tid + 256 * i;
        int n = flat >> 2, c = flat & 3;
        ldg_el8(&fcw[(size_t)(vbase + n) * HH + 8 * c], wv8[i]);
    }
    hr = *(const float4*)&hin[pb * HH + 4 * pc];

    for (int kt = 0; kt < HH; kt += 32) {
        __syncthreads();
#pragma unroll
        for (int i = 0; i < 2; ++i) {
            int flat = tid + 256 * i;
            int n = flat >> 2, c = flat & 3;
#pragma unroll
            for (int j = 0; j < 8; ++j) ws[8 * c + j][n] = wv8[i][j];
        }
        hs[4 * pc + 0][pb] = hr.x;
        hs[4 * pc + 1][pb] = hr.y;
        hs[4 * pc + 2][pb] = hr.z;
        hs[4 * pc + 3][pb] = hr.w;
        __syncthreads();

        if (kt + 32 < HH) {
            int kt2 = kt + 32;
#pragma unroll
            for (int i = 0; i < 2; ++i) {
                int flat = tid + 256 * i;
                int n = flat >> 2, c = flat & 3;
                ldg_el8(&fcw[(size_t)(vbase + n) * HH + kt2 + 8 * c], wv8[i]);
            }
            hr = *(const float4*)&hin[pb * HH + kt2 + 4 * pc];
        }

#pragma unroll
        for (int k = 0; k < 32; ++k) {
            ull wv01 = *(const ull*)&ws[k][4 * tn];
            ull wv23 = *(const ull*)&ws[k][4 * tn + 2];
            float4 hv = *(const float4*)&hs[k][4 * tb];
            ull h0 = pk2(hv.x, hv.x);
            ull h1 = pk2(hv.y, hv.y);
            ull h2 = pk2(hv.z, hv.z);
            ull h3 = pk2(hv.w, hv.w);
            fma2(acc01[0], h0, wv01); fma2(acc23[0], h0, wv23);
            fma2(acc01[1], h1, wv01); fma2(acc23[1], h1, wv23);
            fma2(acc01[2], h2, wv01); fma2(acc23[2], h2, wv23);
            fma2(acc01[3], h3, wv01); fma2(acc23[3], h3, wv23);
        }
    }

    float4 bv = *(const float4*)&fcb[vbase + 4 * tn];

#pragma unroll
    for (int bi = 0; bi < 4; ++bi) {
        int b = 4 * tb + bi;
        float2 a01 = upk2(acc01[bi]);
        float2 a23 = upk2(acc23[bi]);
        float4 lg;
        lg.x = __fadd_rn(a01.x, bv.x);
        lg.y = __fadd_rn(a01.y, bv.y);
        lg.z = __fadd_rn(a23.x, bv.z);
        lg.w = __fadd_rn(a23.y, bv.w);
        __stcs((float4*)&out[((size_t)b * TT + t) * VV + vbase + 4 * tn], lg);

        unsigned long long best = 0ull;
        float lgs[4] = {lg.x, lg.y, lg.z, lg.w};
#pragma unroll
        for (int ni = 0; ni < 4; ++ni) {
            int v = vbase + 4 * tn + ni;
            uint32_t i = (uint32_t)(b * VV + v);
            uint32_t o0, o1;
            threefry2x32(ka, kb, 0u, i, o0, o1);
            uint32_t bits = o0 ^ o1;
            float f = __uint_as_float((bits >> 9) | 0x3f800000u) - 1.0f;
            float u = fmaxf(1.17549435e-38f, f);
            float g = -logf(-logf(u));
            float val = __fadd_rn(lgs[ni], g);
            uint32_t ub = __float_as_uint(val);
            ub = (ub & 0x80000000u) ? ~ub : (ub | 0x80000000u);
            unsigned long long key = ((unsigned long long)ub << 32) |
                (unsigned long long)(0x7fffffffu - (uint32_t)v);
            if (key > best) best = key;
        }
#pragma unroll
        for (int o = 16; o; o >>= 1) {
            unsigned long long other = __shfl_down_sync(0xffffffffu, best, o);
            if (other > best) best = other;
        }
        if (tn == 0) atomicMax(&g_arg[b], best);
    }

    // ---- fused sampler: last block to finish does token select + embed gather
    __threadfence();
    if (tid == 0) {
        unsigned int total = gridDim.x * gridDim.y;
        unsigned int v = atomicAdd(&g_tick, 1u);
        s_last = (v == total - 1u) ? 1u : 0u;
    }
    __syncthreads();
    if (s_last) {
        if (tid == 0) g_tick = 0u;
        __threadfence();
        if (tid < BB) {
            unsigned long long key = g_arg[tid];
            int sampled = 0x7fffffff - (int)(uint32_t)(key & 0xffffffffu);
            int fin = g_fin[tid];
            int token = fin ? PAD_TOK : sampled;
            g_fin[tid] = fin | (sampled == EOS_TOK);
            stok[tid] = token;
            if (has_tok) tok_out[(size_t)tid * TT + t] = (float)token;
        }
        __syncthreads();
        for (int i = tid; i < BB * DD / 4; i += 256) {
            int b = i >> 7;
            int c = i & 127;
            ((float4*)xout)[b * 128 + c] =
                ((const float4*)embed)[(size_t)stok[b] * 128 + c];
        }
    }
}

// ---------------- host launch --------------------------------------------------
extern "C" void kernel_launch(void* const* d_in, const int* in_sizes, int n_in,
                              void* d_out, int out_size)
{
    const float* input_seq = (const float*)d_in[0];
    const float* h_enc     = (const float*)d_in[1];
    const float* c_enc     = (const float*)d_in[2];
    const float* W_ih      = (const float*)d_in[3];
    const float* W_hh      = (const float*)d_in[4];
    const float* b_ih      = (const float*)d_in[5];
    const float* b_hh      = (const float*)d_in[6];
    const float* fc_w      = (const float*)d_in[7];
    const float* fc_b      = (const float*)d_in[8];
    const float* embed     = (const float*)d_in[9];
    float* out = (float*)d_out;

    long long need_tok = (long long)BB * TT * VV + (long long)BB * TT;
    int has_tok = ((long long)out_size >= need_tok) ? 1 : 0;
    float* tok_out = out + (size_t)BB * TT * VV;

    float *hb, *cb, *xb;
    cudaGetSymbolAddress((void**)&hb, g_h);
    cudaGetSymbolAddress((void**)&cb, g_c);
    cudaGetSymbolAddress((void**)&xb, g_x);
#define HP(p, lyr) (hb + (((p) * LL) + (lyr)) * (BB * HH))
#define CP(p, lyr) (cb + (((p) * LL) + (lyr)) * (BB * HH))
#define XP(p)      (xb + (p) * (BB * DD))

    k_init<<<64, 512>>>(input_seq, h_enc, c_enc, HP(0, 0), CP(0, 0), XP(0));

    for (int t = 0; t < TT; ++t) {
        int p = t & 1, q = p ^ 1;

        k_lstm<<<128, 256>>>(XP(p), HP(p, 0), CP(p, 0),
                             HP(q, 0), CP(q, 0),
                             W_ih, W_hh, b_ih, b_hh, /*clearArg=*/1);
        k_lstm<<<128, 256>>>(HP(q, 0), HP(p, 1), CP(p, 1),
                             HP(q, 1), CP(q, 1),
                             W_ih + (size_t)G4 * DD,
                             W_hh + (size_t)G4 * HH,
                             b_ih + G4, b_hh + G4, /*clearArg=*/0);

        uint32_t ka, kb;
        threefry2x32(0u, 42u, 0u, (uint32_t)t, ka, kb);

        k_logits<<<250, 256>>>(HP(q, 1), fc_w, fc_b, out,
                               XP(q), embed, tok_out, t, has_tok, ka, kb);
    }
#undef HP
#undef CP
#undef XP
}